// round 1
// baseline (speedup 1.0000x reference)
#include <cuda_runtime.h>
#include <cuda_bf16.h>
#include <math.h>

// Problem constants
#define B_  4
#define L_  2048
#define D_  1024
#define H_  16
#define KD_ 64
#define M_  (B_ * L_)        // 8192 rows of tokens
#define EPS_ 1e-5f

// ---------------- scratch (device globals; no allocation allowed) ----------
__device__ float g_q[M_ * D_];
__device__ float g_k[M_ * D_];
__device__ float g_v[M_ * D_];
__device__ float g_o[M_ * D_];
__device__ float g_res[M_ * D_];

// ---------------- generic tiled SGEMM: C = A@W + bias (+Res) ---------------
// A [M,K] row-major, W [K,N] row-major. BM=BN=64, BK=16, 256 threads,
// each thread computes a 4x4 micro-tile. M,N,K assumed multiples of tile dims.
#define BM 64
#define BN 64
#define BK 16

__global__ __launch_bounds__(256) void sgemm_bias_res(
    const float* __restrict__ A, const float* __restrict__ W,
    const float* __restrict__ bias, const float* __restrict__ Res,
    float* __restrict__ C, int M, int N, int K)
{
    __shared__ __align__(16) float As[BK][BM];
    __shared__ __align__(16) float Bs[BK][BN];

    const int tid = threadIdx.x;
    const int tx = tid & 15;          // 0..15 (col group)
    const int ty = tid >> 4;          // 0..15 (row group)
    const int row0 = blockIdx.y * BM;
    const int col0 = blockIdx.x * BN;

    // A tile load mapping: thread -> (row ar, 4-col group ac)
    const int ar = tid >> 2;          // 0..63
    const int ac = (tid & 3) * 4;     // 0,4,8,12
    // B tile load mapping
    const int br = tid >> 4;          // 0..15
    const int bc = (tid & 15) * 4;    // 0..60

    float acc[4][4];
#pragma unroll
    for (int i = 0; i < 4; i++)
#pragma unroll
        for (int j = 0; j < 4; j++) acc[i][j] = 0.f;

    for (int k0 = 0; k0 < K; k0 += BK) {
        float4 av = *(const float4*)&A[(size_t)(row0 + ar) * K + k0 + ac];
        float4 bv = *(const float4*)&W[(size_t)(k0 + br) * N + col0 + bc];
        // transpose-store A into As[k][m]
        As[ac + 0][ar] = av.x;
        As[ac + 1][ar] = av.y;
        As[ac + 2][ar] = av.z;
        As[ac + 3][ar] = av.w;
        *(float4*)&Bs[br][bc] = bv;
        __syncthreads();

#pragma unroll
        for (int k = 0; k < BK; ++k) {
            float4 a = *(const float4*)&As[k][ty * 4];
            float4 b = *(const float4*)&Bs[k][tx * 4];
            float av4[4] = {a.x, a.y, a.z, a.w};
            float bv4[4] = {b.x, b.y, b.z, b.w};
#pragma unroll
            for (int i = 0; i < 4; i++)
#pragma unroll
                for (int j = 0; j < 4; j++)
                    acc[i][j] = fmaf(av4[i], bv4[j], acc[i][j]);
        }
        __syncthreads();
    }

    // epilogue: bias (+ residual) + store, vectorized
    float4 bb = *(const float4*)&bias[col0 + tx * 4];
#pragma unroll
    for (int i = 0; i < 4; i++) {
        int r = row0 + ty * 4 + i;
        size_t off = (size_t)r * N + col0 + tx * 4;
        float4 out;
        out.x = acc[i][0] + bb.x;
        out.y = acc[i][1] + bb.y;
        out.z = acc[i][2] + bb.z;
        out.w = acc[i][3] + bb.w;
        if (Res) {
            float4 rv = *(const float4*)&Res[off];
            out.x += rv.x; out.y += rv.y; out.z += rv.z; out.w += rv.w;
        }
        *(float4*)&C[off] = out;
    }
}

// ---------------- flash attention: 1 thread = 1 query row ------------------
// Layouts: Q/K/V/O all [B][L][H][64] (row for (b,l,h) at ((b*L+l)*H+h)*64).
#define AT_THREADS 128
#define KTILE 32
#define NTILES (L_ / KTILE)

__global__ __launch_bounds__(AT_THREADS) void attn_kernel(
    const float* __restrict__ Q, const float* __restrict__ Kb,
    const float* __restrict__ Vb, float* __restrict__ O)
{
    __shared__ float4 Ks[KTILE][16];
    __shared__ float4 Vs[KTILE][16];
    __shared__ float  Ss[AT_THREADS][KTILE + 1];

    const int b = blockIdx.z;
    const int h = blockIdx.y;
    const int tid = threadIdx.x;
    const int l = blockIdx.x * AT_THREADS + tid;

    const float* qrow = Q + (((size_t)b * L_ + l) * H_ + h) * KD_;
    float4 q4[16];
#pragma unroll
    for (int i = 0; i < 16; i++) q4[i] = ((const float4*)qrow)[i];

    float4 acc[16];
#pragma unroll
    for (int i = 0; i < 16; i++) acc[i] = make_float4(0.f, 0.f, 0.f, 0.f);
    float m = -INFINITY, lsum = 0.f;

    const float* Kbase = Kb + ((size_t)b * L_ * H_ + h) * KD_;  // key j at +j*H_*KD_
    const float* Vbase = Vb + ((size_t)b * L_ * H_ + h) * KD_;
    const int rowstride = H_ * KD_;  // 1024 floats

    for (int t = 0; t < NTILES; ++t) {
        __syncthreads();
        // cooperative load of K/V tile: KTILE*16 float4 each, 4 per thread
#pragma unroll
        for (int i = 0; i < 4; ++i) {
            int f = tid + i * AT_THREADS;       // 0..511
            int r = f >> 4, c = f & 15;
            Ks[r][c] = ((const float4*)(Kbase + (size_t)(t * KTILE + r) * rowstride))[c];
            Vs[r][c] = ((const float4*)(Vbase + (size_t)(t * KTILE + r) * rowstride))[c];
        }
        __syncthreads();

        // pass 1: scores + tile max
        float tmax = -INFINITY;
#pragma unroll 4
        for (int j = 0; j < KTILE; ++j) {
            float4 s4 = make_float4(0.f, 0.f, 0.f, 0.f);
#pragma unroll
            for (int d = 0; d < 16; ++d) {
                float4 kk = Ks[j][d];
                s4.x = fmaf(q4[d].x, kk.x, s4.x);
                s4.y = fmaf(q4[d].y, kk.y, s4.y);
                s4.z = fmaf(q4[d].z, kk.z, s4.z);
                s4.w = fmaf(q4[d].w, kk.w, s4.w);
            }
            float s = (s4.x + s4.y + s4.z + s4.w) * 0.125f;  // 1/sqrt(64)
            Ss[tid][j] = s;
            tmax = fmaxf(tmax, s);
        }

        // online-softmax rescale
        float mnew = fmaxf(m, tmax);
        float corr = __expf(m - mnew);   // exp(-inf)=0 handles first tile
        lsum *= corr;
#pragma unroll
        for (int d = 0; d < 16; ++d) {
            acc[d].x *= corr; acc[d].y *= corr; acc[d].z *= corr; acc[d].w *= corr;
        }
        m = mnew;

        // pass 2: P@V
#pragma unroll 2
        for (int j = 0; j < KTILE; ++j) {
            float p = __expf(Ss[tid][j] - m);
            lsum += p;
#pragma unroll
            for (int d = 0; d < 16; ++d) {
                float4 vv = Vs[j][d];
                acc[d].x = fmaf(p, vv.x, acc[d].x);
                acc[d].y = fmaf(p, vv.y, acc[d].y);
                acc[d].z = fmaf(p, vv.z, acc[d].z);
                acc[d].w = fmaf(p, vv.w, acc[d].w);
            }
        }
    }

    float inv = 1.f / lsum;
    float4* orow = (float4*)(O + (((size_t)b * L_ + l) * H_ + h) * KD_);
#pragma unroll
    for (int d = 0; d < 16; ++d) {
        float4 o = acc[d];
        o.x *= inv; o.y *= inv; o.z *= inv; o.w *= inv;
        orow[d] = o;
    }
}

// ---------------- LayerNorm: one block per row -----------------------------
__global__ __launch_bounds__(256) void ln_kernel(
    const float* __restrict__ X, const float* __restrict__ gamma,
    const float* __restrict__ beta, float* __restrict__ Y)
{
    const int row = blockIdx.x;
    const int tid = threadIdx.x;
    const float4* x = (const float4*)(X + (size_t)row * D_);
    float4 v = x[tid];                       // 256 threads * 4 = 1024 elems

    float s  = v.x + v.y + v.z + v.w;
    float sq = v.x * v.x + v.y * v.y + v.z * v.z + v.w * v.w;

    // warp reduce
#pragma unroll
    for (int off = 16; off > 0; off >>= 1) {
        s  += __shfl_xor_sync(0xffffffff, s, off);
        sq += __shfl_xor_sync(0xffffffff, sq, off);
    }
    __shared__ float2 red[8];
    if ((tid & 31) == 0) red[tid >> 5] = make_float2(s, sq);
    __syncthreads();
    if (tid < 8) {
        float2 r = red[tid];
#pragma unroll
        for (int off = 4; off > 0; off >>= 1) {
            r.x += __shfl_xor_sync(0xff, r.x, off);
            r.y += __shfl_xor_sync(0xff, r.y, off);
        }
        if (tid == 0) red[0] = r;
    }
    __syncthreads();
    float mean = red[0].x * (1.f / D_);
    float var  = red[0].y * (1.f / D_) - mean * mean;
    float rstd = rsqrtf(var + EPS_);

    float4 g = ((const float4*)gamma)[tid];
    float4 bt = ((const float4*)beta)[tid];
    float4 o;
    o.x = (v.x - mean) * rstd * g.x + bt.x;
    o.y = (v.y - mean) * rstd * g.y + bt.y;
    o.z = (v.z - mean) * rstd * g.z + bt.z;
    o.w = (v.w - mean) * rstd * g.w + bt.w;
    ((float4*)(Y + (size_t)row * D_))[tid] = o;
}

// ---------------- host launch ----------------------------------------------
extern "C" void kernel_launch(void* const* d_in, const int* in_sizes, int n_in,
                              void* d_out, int out_size)
{
    const float* queries = (const float*)d_in[0];
    const float* Wq = (const float*)d_in[1];
    const float* bq = (const float*)d_in[2];
    const float* Wk = (const float*)d_in[3];
    const float* bk = (const float*)d_in[4];
    const float* Wv = (const float*)d_in[5];
    const float* bv = (const float*)d_in[6];
    const float* Wo = (const float*)d_in[7];
    const float* bo = (const float*)d_in[8];
    const float* gamma = (const float*)d_in[9];
    const float* beta  = (const float*)d_in[10];

    float *q, *k, *v, *o, *res;
    cudaGetSymbolAddress((void**)&q,   g_q);
    cudaGetSymbolAddress((void**)&k,   g_k);
    cudaGetSymbolAddress((void**)&v,   g_v);
    cudaGetSymbolAddress((void**)&o,   g_o);
    cudaGetSymbolAddress((void**)&res, g_res);

    dim3 gGrid(D_ / BN, M_ / BM);   // (16, 128)

    sgemm_bias_res<<<gGrid, 256>>>(queries, Wq, bq, nullptr, q, M_, D_, D_);
    sgemm_bias_res<<<gGrid, 256>>>(queries, Wk, bk, nullptr, k, M_, D_, D_);
    sgemm_bias_res<<<gGrid, 256>>>(queries, Wv, bv, nullptr, v, M_, D_, D_);

    attn_kernel<<<dim3(L_ / AT_THREADS, H_, B_), AT_THREADS>>>(q, k, v, o);

    sgemm_bias_res<<<gGrid, 256>>>(o, Wo, bo, queries, res, M_, D_, D_);

    ln_kernel<<<M_, 256>>>(res, gamma, beta, (float*)d_out);
}

// round 3
// speedup vs baseline: 1.4543x; 1.4543x over previous
#include <cuda_runtime.h>
#include <cuda_bf16.h>
#include <math.h>
#include <stdint.h>

// Problem constants
#define B_  4
#define L_  2048
#define D_  1024
#define H_  16
#define KD_ 64
#define M_  (B_ * L_)        // 8192 token rows
#define EPS_ 1e-5f

// ---------------- scratch (device globals; no allocation allowed) ----------
__device__ float g_q[M_ * D_];
__device__ float g_k[M_ * D_];
__device__ float g_v[M_ * D_];
__device__ float g_o[M_ * D_];
__device__ float g_res[M_ * D_];
__device__ float g_qr[M_ * D_];     // tf32-rounded copy of queries (MMA operand)
__device__ float g_wqt[D_ * D_];
__device__ float g_wkt[D_ * D_];
__device__ float g_wvt[D_ * D_];
__device__ float g_wot[D_ * D_];

// ---------------- helpers ---------------------------------------------------
__device__ __forceinline__ float tf32r(float x) {
    uint32_t u;
    asm("cvt.rna.tf32.f32 %0, %1;" : "=r"(u) : "f"(x));
    return __uint_as_float(u);
}

__device__ __forceinline__ void mma_tf32(float* d, const uint32_t* a, const uint32_t* b) {
    asm volatile(
        "mma.sync.aligned.m16n8k8.row.col.f32.tf32.tf32.f32 "
        "{%0,%1,%2,%3}, {%4,%5,%6,%7}, {%8,%9}, {%0,%1,%2,%3};\n"
        : "+f"(d[0]), "+f"(d[1]), "+f"(d[2]), "+f"(d[3])
        : "r"(a[0]), "r"(a[1]), "r"(a[2]), "r"(a[3]), "r"(b[0]), "r"(b[1]));
}

// ================= tf32 warp-MMA GEMM ======================================
// C[8192,1024] = A@Bt^T + bias (+Res).  A[M,1024] row-major (tf32-rounded),
// Bt[1024,1024] row-major = W^T (tf32-rounded).  Tile 128x128, BK=32.
// 8 warps: wm in {0,1} (64 rows), wn in {0..3} (32 cols).
#define GSTRIDE 36   // smem row stride in floats -> conflict-free frag LDS

__global__ __launch_bounds__(256) void gemm_mma(
    const float* __restrict__ A, const float* __restrict__ Bt,
    const float* __restrict__ bias, const float* __restrict__ Res,
    float* __restrict__ C)
{
    __shared__ uint32_t As[128 * GSTRIDE];
    __shared__ uint32_t Bs[128 * GSTRIDE];

    const int tid  = threadIdx.x;
    const int wid  = tid >> 5;
    const int lane = tid & 31;
    const int wm = wid & 1;          // 0..1
    const int wn = wid >> 1;         // 0..3
    const int qr = lane >> 2;        // 0..7
    const int ql = lane & 3;         // 0..3

    const int row0 = blockIdx.y * 128;
    const int col0 = blockIdx.x * 128;

    float acc[4][4][4];
#pragma unroll
    for (int i = 0; i < 4; i++)
#pragma unroll
        for (int j = 0; j < 4; j++)
#pragma unroll
            for (int r = 0; r < 4; r++) acc[i][j][r] = 0.f;

    // fill mapping: f = i*256+tid -> row f>>3 (0..127), 16B chunk f&7
    int fr[4], fc[4];
    const float* Aptr[4]; const float* Bptr[4];
#pragma unroll
    for (int i = 0; i < 4; i++) {
        int f = i * 256 + tid;
        fr[i] = f >> 3;
        fc[i] = (f & 7) * 4;
        Aptr[i] = A  + (size_t)(row0 + fr[i]) * D_ + fc[i];
        Bptr[i] = Bt + (size_t)(col0 + fr[i]) * D_ + fc[i];
    }

    float4 pa[4], pb[4];
#pragma unroll
    for (int i = 0; i < 4; i++) {
        pa[i] = *(const float4*)(Aptr[i]);
        pb[i] = *(const float4*)(Bptr[i]);
    }

    const int mb0 = wm * 64;
    const int nb0 = wn * 32;

    for (int c = 0; c < D_ / 32; ++c) {
        // store current chunk to smem
#pragma unroll
        for (int i = 0; i < 4; i++) {
            *(uint4*)&As[fr[i] * GSTRIDE + fc[i]] = *(uint4*)&pa[i];
            *(uint4*)&Bs[fr[i] * GSTRIDE + fc[i]] = *(uint4*)&pb[i];
        }
        __syncthreads();

        // prefetch next chunk
        if (c + 1 < D_ / 32) {
            const int k0 = (c + 1) * 32;
#pragma unroll
            for (int i = 0; i < 4; i++) {
                pa[i] = *(const float4*)(Aptr[i] + k0);
                pb[i] = *(const float4*)(Bptr[i] + k0);
            }
        }

        // compute 4 k-steps of m16n8k8
#pragma unroll
        for (int ks = 0; ks < 4; ++ks) {
            uint32_t af[4][4], bf[4][2];
#pragma unroll
            for (int mt = 0; mt < 4; ++mt) {
                int rbase = (mb0 + mt * 16 + qr) * GSTRIDE + ks * 8 + ql;
                af[mt][0] = As[rbase];
                af[mt][1] = As[rbase + 8 * GSTRIDE];
                af[mt][2] = As[rbase + 4];
                af[mt][3] = As[rbase + 8 * GSTRIDE + 4];
            }
#pragma unroll
            for (int nt = 0; nt < 4; ++nt) {
                int rbase = (nb0 + nt * 8 + qr) * GSTRIDE + ks * 8 + ql;
                bf[nt][0] = Bs[rbase];
                bf[nt][1] = Bs[rbase + 4];
            }
#pragma unroll
            for (int mt = 0; mt < 4; ++mt)
#pragma unroll
                for (int nt = 0; nt < 4; ++nt)
                    mma_tf32(acc[mt][nt], af[mt], bf[nt]);
        }
        __syncthreads();
    }

    // epilogue: c0/c1 at (row, col), c2/c3 at (row+8, col); col pair contiguous
#pragma unroll
    for (int mt = 0; mt < 4; ++mt) {
        int row_lo = row0 + mb0 + mt * 16 + qr;
#pragma unroll
        for (int nt = 0; nt < 4; ++nt) {
            int col = col0 + nb0 + nt * 8 + ql * 2;
            float2 bb = *(const float2*)&bias[col];
            size_t off_lo = (size_t)row_lo * D_ + col;
            size_t off_hi = off_lo + (size_t)8 * D_;
            float2 o_lo, o_hi;
            o_lo.x = acc[mt][nt][0] + bb.x;
            o_lo.y = acc[mt][nt][1] + bb.y;
            o_hi.x = acc[mt][nt][2] + bb.x;
            o_hi.y = acc[mt][nt][3] + bb.y;
            if (Res) {
                float2 r0 = *(const float2*)&Res[off_lo];
                float2 r1 = *(const float2*)&Res[off_hi];
                o_lo.x += r0.x; o_lo.y += r0.y;
                o_hi.x += r1.x; o_hi.y += r1.y;
            }
            *(float2*)&C[off_lo] = o_lo;
            *(float2*)&C[off_hi] = o_hi;
        }
    }
}

// ---------------- elementwise tf32 rounding pass ---------------------------
__global__ __launch_bounds__(256) void round_tf32_kernel(
    const float* __restrict__ X, float* __restrict__ Y)
{
    int i = blockIdx.x * 256 + threadIdx.x;
    float4 v = ((const float4*)X)[i];
    float4 o;
    o.x = tf32r(v.x); o.y = tf32r(v.y); o.z = tf32r(v.z); o.w = tf32r(v.w);
    ((float4*)Y)[i] = o;
}

// ---------------- weight transpose + tf32 round: Wt[n][k] = r(W[k][n]) -----
__global__ __launch_bounds__(256) void transpose4(
    const float* __restrict__ W0, const float* __restrict__ W1,
    const float* __restrict__ W2, const float* __restrict__ W3,
    float* __restrict__ T0, float* __restrict__ T1,
    float* __restrict__ T2, float* __restrict__ T3)
{
    __shared__ float tile[32][33];
    const float* W; float* T;
    switch (blockIdx.z) {
        case 0: W = W0; T = T0; break;
        case 1: W = W1; T = T1; break;
        case 2: W = W2; T = T2; break;
        default: W = W3; T = T3; break;
    }
    int tx = threadIdx.x, ty = threadIdx.y;   // 32 x 8
    int x = blockIdx.x * 32 + tx;
    int y = blockIdx.y * 32 + ty;
#pragma unroll
    for (int i = 0; i < 4; ++i)
        tile[ty + 8 * i][tx] = W[(size_t)(y + 8 * i) * D_ + x];
    __syncthreads();
    int x2 = blockIdx.y * 32 + tx;
    int y2 = blockIdx.x * 32 + ty;
#pragma unroll
    for (int i = 0; i < 4; ++i)
        T[(size_t)(y2 + 8 * i) * D_ + x2] = tf32r(tile[tx][ty + 8 * i]);
}

// ---------------- flash attention: 1 thread = 1 query row ------------------
#define AT_THREADS 128
#define KTILE 32
#define NTILES (L_ / KTILE)

__global__ __launch_bounds__(AT_THREADS) void attn_kernel(
    const float* __restrict__ Q, const float* __restrict__ Kb,
    const float* __restrict__ Vb, float* __restrict__ O)
{
    __shared__ float4 Ks[KTILE][16];
    __shared__ float4 Vs[KTILE][16];
    __shared__ float  Ss[AT_THREADS][KTILE + 1];

    const int b = blockIdx.z;
    const int h = blockIdx.y;
    const int tid = threadIdx.x;
    const int l = blockIdx.x * AT_THREADS + tid;

    const float* qrow = Q + (((size_t)b * L_ + l) * H_ + h) * KD_;
    float4 q4[16];
#pragma unroll
    for (int i = 0; i < 16; i++) q4[i] = ((const float4*)qrow)[i];

    float4 acc[16];
#pragma unroll
    for (int i = 0; i < 16; i++) acc[i] = make_float4(0.f, 0.f, 0.f, 0.f);
    float m = -INFINITY, lsum = 0.f;

    const float* Kbase = Kb + ((size_t)b * L_ * H_ + h) * KD_;
    const float* Vbase = Vb + ((size_t)b * L_ * H_ + h) * KD_;
    const int rowstride = H_ * KD_;

    for (int t = 0; t < NTILES; ++t) {
        __syncthreads();
#pragma unroll
        for (int i = 0; i < 4; ++i) {
            int f = tid + i * AT_THREADS;
            int r = f >> 4, c = f & 15;
            Ks[r][c] = ((const float4*)(Kbase + (size_t)(t * KTILE + r) * rowstride))[c];
            Vs[r][c] = ((const float4*)(Vbase + (size_t)(t * KTILE + r) * rowstride))[c];
        }
        __syncthreads();

        float tmax = -INFINITY;
#pragma unroll 4
        for (int j = 0; j < KTILE; ++j) {
            float4 s4 = make_float4(0.f, 0.f, 0.f, 0.f);
#pragma unroll
            for (int d = 0; d < 16; ++d) {
                float4 kk = Ks[j][d];
                s4.x = fmaf(q4[d].x, kk.x, s4.x);
                s4.y = fmaf(q4[d].y, kk.y, s4.y);
                s4.z = fmaf(q4[d].z, kk.z, s4.z);
                s4.w = fmaf(q4[d].w, kk.w, s4.w);
            }
            float s = (s4.x + s4.y + s4.z + s4.w) * 0.125f;
            Ss[tid][j] = s;
            tmax = fmaxf(tmax, s);
        }

        float mnew = fmaxf(m, tmax);
        float corr = __expf(m - mnew);
        lsum *= corr;
#pragma unroll
        for (int d = 0; d < 16; ++d) {
            acc[d].x *= corr; acc[d].y *= corr; acc[d].z *= corr; acc[d].w *= corr;
        }
        m = mnew;

#pragma unroll 2
        for (int j = 0; j < KTILE; ++j) {
            float p = __expf(Ss[tid][j] - m);
            lsum += p;
#pragma unroll
            for (int d = 0; d < 16; ++d) {
                float4 vv = Vs[j][d];
                acc[d].x = fmaf(p, vv.x, acc[d].x);
                acc[d].y = fmaf(p, vv.y, acc[d].y);
                acc[d].z = fmaf(p, vv.z, acc[d].z);
                acc[d].w = fmaf(p, vv.w, acc[d].w);
            }
        }
    }

    // store tf32-rounded so the Wo GEMM operand is already rounded
    float inv = 1.f / lsum;
    float4* orow = (float4*)(O + (((size_t)b * L_ + l) * H_ + h) * KD_);
#pragma unroll
    for (int d = 0; d < 16; ++d) {
        float4 o = acc[d];
        o.x = tf32r(o.x * inv); o.y = tf32r(o.y * inv);
        o.z = tf32r(o.z * inv); o.w = tf32r(o.w * inv);
        orow[d] = o;
    }
}

// ---------------- LayerNorm: one block per row -----------------------------
__global__ __launch_bounds__(256) void ln_kernel(
    const float* __restrict__ X, const float* __restrict__ gamma,
    const float* __restrict__ beta, float* __restrict__ Y)
{
    const int row = blockIdx.x;
    const int tid = threadIdx.x;
    const float4* x = (const float4*)(X + (size_t)row * D_);
    float4 v = x[tid];

    float s  = v.x + v.y + v.z + v.w;
    float sq = v.x * v.x + v.y * v.y + v.z * v.z + v.w * v.w;
#pragma unroll
    for (int off = 16; off > 0; off >>= 1) {
        s  += __shfl_xor_sync(0xffffffff, s, off);
        sq += __shfl_xor_sync(0xffffffff, sq, off);
    }
    __shared__ float2 red[8];
    if ((tid & 31) == 0) red[tid >> 5] = make_float2(s, sq);
    __syncthreads();
    if (tid < 8) {
        float2 r = red[tid];
#pragma unroll
        for (int off = 4; off > 0; off >>= 1) {
            r.x += __shfl_xor_sync(0xff, r.x, off);
            r.y += __shfl_xor_sync(0xff, r.y, off);
        }
        if (tid == 0) red[0] = r;
    }
    __syncthreads();
    float mean = red[0].x * (1.f / D_);
    float var  = red[0].y * (1.f / D_) - mean * mean;
    float rstd = rsqrtf(var + EPS_);

    float4 g = ((const float4*)gamma)[tid];
    float4 bt = ((const float4*)beta)[tid];
    float4 o;
    o.x = (v.x - mean) * rstd * g.x + bt.x;
    o.y = (v.y - mean) * rstd * g.y + bt.y;
    o.z = (v.z - mean) * rstd * g.z + bt.z;
    o.w = (v.w - mean) * rstd * g.w + bt.w;
    ((float4*)(Y + (size_t)row * D_))[tid] = o;
}

// ---------------- host launch ----------------------------------------------
extern "C" void kernel_launch(void* const* d_in, const int* in_sizes, int n_in,
                              void* d_out, int out_size)
{
    const float* queries = (const float*)d_in[0];
    const float* Wq = (const float*)d_in[1];
    const float* bq = (const float*)d_in[2];
    const float* Wk = (const float*)d_in[3];
    const float* bk = (const float*)d_in[4];
    const float* Wv = (const float*)d_in[5];
    const float* bv = (const float*)d_in[6];
    const float* Wo = (const float*)d_in[7];
    const float* bo = (const float*)d_in[8];
    const float* gamma = (const float*)d_in[9];
    const float* beta  = (const float*)d_in[10];

    float *q, *k, *v, *o, *res, *qr, *wqt, *wkt, *wvt, *wot;
    cudaGetSymbolAddress((void**)&q,   g_q);
    cudaGetSymbolAddress((void**)&k,   g_k);
    cudaGetSymbolAddress((void**)&v,   g_v);
    cudaGetSymbolAddress((void**)&o,   g_o);
    cudaGetSymbolAddress((void**)&res, g_res);
    cudaGetSymbolAddress((void**)&qr,  g_qr);
    cudaGetSymbolAddress((void**)&wqt, g_wqt);
    cudaGetSymbolAddress((void**)&wkt, g_wkt);
    cudaGetSymbolAddress((void**)&wvt, g_wvt);
    cudaGetSymbolAddress((void**)&wot, g_wot);

    // prep: rounded activation copy + rounded transposed weights
    round_tf32_kernel<<<(M_ * D_) / (256 * 4), 256>>>(queries, qr);
    transpose4<<<dim3(32, 32, 4), dim3(32, 8)>>>(Wq, Wk, Wv, Wo, wqt, wkt, wvt, wot);

    dim3 gGrid(D_ / 128, M_ / 128);   // (8, 64)
    gemm_mma<<<gGrid, 256>>>(qr, wqt, bq, nullptr, q);
    gemm_mma<<<gGrid, 256>>>(qr, wkt, bk, nullptr, k);
    gemm_mma<<<gGrid, 256>>>(qr, wvt, bv, nullptr, v);

    attn_kernel<<<dim3(L_ / AT_THREADS, H_, B_), AT_THREADS>>>(q, k, v, o);

    gemm_mma<<<gGrid, 256>>>(o, wot, bo, queries, res);

    ln_kernel<<<M_, 256>>>(res, gamma, beta, (float*)d_out);
}

// round 7
// speedup vs baseline: 3.7426x; 2.5735x over previous
#include <cuda_runtime.h>
#include <cuda_bf16.h>
#include <math.h>
#include <stdint.h>

// Problem constants
#define B_  4
#define L_  2048
#define D_  1024
#define H_  16
#define KD_ 64
#define M_  (B_ * L_)        // 8192 token rows
#define EPS_ 1e-5f

// ---------------- scratch (device globals; no allocation allowed) ----------
__device__ float g_q[M_ * D_];
__device__ float g_k[M_ * D_];
__device__ float g_v[M_ * D_];
__device__ float g_o[M_ * D_];
__device__ float g_res[M_ * D_];
__device__ float g_qr[M_ * D_];     // tf32-rounded copy of queries (MMA operand)
__device__ float g_wqt[D_ * D_];
__device__ float g_wkt[D_ * D_];
__device__ float g_wvt[D_ * D_];
__device__ float g_wot[D_ * D_];

// ---------------- helpers ---------------------------------------------------
__device__ __forceinline__ float tf32r(float x) {
    uint32_t u;
    asm("cvt.rna.tf32.f32 %0, %1;" : "=r"(u) : "f"(x));
    return __uint_as_float(u);
}

__device__ __forceinline__ void mma_tf32(float* d, const uint32_t* a, const uint32_t* b) {
    asm volatile(
        "mma.sync.aligned.m16n8k8.row.col.f32.tf32.tf32.f32 "
        "{%0,%1,%2,%3}, {%4,%5,%6,%7}, {%8,%9}, {%0,%1,%2,%3};\n"
        : "+f"(d[0]), "+f"(d[1]), "+f"(d[2]), "+f"(d[3])
        : "r"(a[0]), "r"(a[1]), "r"(a[2]), "r"(a[3]), "r"(b[0]), "r"(b[1]));
}

__device__ __forceinline__ void mma_tf32_4(float* d,
    uint32_t a0, uint32_t a1, uint32_t a2, uint32_t a3,
    uint32_t b0, uint32_t b1) {
    asm volatile(
        "mma.sync.aligned.m16n8k8.row.col.f32.tf32.tf32.f32 "
        "{%0,%1,%2,%3}, {%4,%5,%6,%7}, {%8,%9}, {%0,%1,%2,%3};\n"
        : "+f"(d[0]), "+f"(d[1]), "+f"(d[2]), "+f"(d[3])
        : "r"(a0), "r"(a1), "r"(a2), "r"(a3), "r"(b0), "r"(b1));
}

__device__ __forceinline__ uint32_t smem_u32(const void* p) {
    uint32_t a;
    asm("{ .reg .u64 t; cvta.to.shared.u64 t, %1; cvt.u32.u64 %0, t; }"
        : "=r"(a) : "l"(p));
    return a;
}
#define CP_ASYNC16(dst_u32, src_ptr) \
    asm volatile("cp.async.cg.shared.global [%0], [%1], 16;" \
        :: "r"(dst_u32), "l"(src_ptr))
#define CP_COMMIT() asm volatile("cp.async.commit_group;" ::: "memory")
#define CP_WAIT_ALL() asm volatile("cp.async.wait_all;" ::: "memory")

// ================= tf32 warp-MMA GEMM ======================================
// C[8192,1024] = A@Bt^T + bias (+Res).  Tile 128x128, BK=32, 8 warps (2x4).
#define GSTRIDE 36   // smem row stride in floats -> conflict-free frag LDS

__global__ __launch_bounds__(256) void gemm_mma(
    const float* __restrict__ A, const float* __restrict__ Bt,
    const float* __restrict__ bias, const float* __restrict__ Res,
    float* __restrict__ C, int rnd)
{
    __shared__ uint32_t As[128 * GSTRIDE];
    __shared__ uint32_t Bs[128 * GSTRIDE];

    const int tid  = threadIdx.x;
    const int wid  = tid >> 5;
    const int lane = tid & 31;
    const int wm = wid & 1;
    const int wn = wid >> 1;
    const int qr = lane >> 2;
    const int ql = lane & 3;

    const int row0 = blockIdx.y * 128;
    const int col0 = blockIdx.x * 128;

    float acc[4][4][4];
#pragma unroll
    for (int i = 0; i < 4; i++)
#pragma unroll
        for (int j = 0; j < 4; j++)
#pragma unroll
            for (int r = 0; r < 4; r++) acc[i][j][r] = 0.f;

    int fr[4], fc[4];
    const float* Aptr[4]; const float* Bptr[4];
#pragma unroll
    for (int i = 0; i < 4; i++) {
        int f = i * 256 + tid;
        fr[i] = f >> 3;
        fc[i] = (f & 7) * 4;
        Aptr[i] = A  + (size_t)(row0 + fr[i]) * D_ + fc[i];
        Bptr[i] = Bt + (size_t)(col0 + fr[i]) * D_ + fc[i];
    }

    float4 pa[4], pb[4];
#pragma unroll
    for (int i = 0; i < 4; i++) {
        pa[i] = *(const float4*)(Aptr[i]);
        pb[i] = *(const float4*)(Bptr[i]);
    }

    const int mb0 = wm * 64;
    const int nb0 = wn * 32;

    for (int c = 0; c < D_ / 32; ++c) {
#pragma unroll
        for (int i = 0; i < 4; i++) {
            *(uint4*)&As[fr[i] * GSTRIDE + fc[i]] = *(uint4*)&pa[i];
            *(uint4*)&Bs[fr[i] * GSTRIDE + fc[i]] = *(uint4*)&pb[i];
        }
        __syncthreads();

        if (c + 1 < D_ / 32) {
            const int k0 = (c + 1) * 32;
#pragma unroll
            for (int i = 0; i < 4; i++) {
                pa[i] = *(const float4*)(Aptr[i] + k0);
                pb[i] = *(const float4*)(Bptr[i] + k0);
            }
        }

#pragma unroll
        for (int ks = 0; ks < 4; ++ks) {
            uint32_t af[4][4], bf[4][2];
#pragma unroll
            for (int mt = 0; mt < 4; ++mt) {
                int rbase = (mb0 + mt * 16 + qr) * GSTRIDE + ks * 8 + ql;
                af[mt][0] = As[rbase];
                af[mt][1] = As[rbase + 8 * GSTRIDE];
                af[mt][2] = As[rbase + 4];
                af[mt][3] = As[rbase + 8 * GSTRIDE + 4];
            }
#pragma unroll
            for (int nt = 0; nt < 4; ++nt) {
                int rbase = (nb0 + nt * 8 + qr) * GSTRIDE + ks * 8 + ql;
                bf[nt][0] = Bs[rbase];
                bf[nt][1] = Bs[rbase + 4];
            }
#pragma unroll
            for (int mt = 0; mt < 4; ++mt)
#pragma unroll
                for (int nt = 0; nt < 4; ++nt)
                    mma_tf32(acc[mt][nt], af[mt], bf[nt]);
        }
        __syncthreads();
    }

#pragma unroll
    for (int mt = 0; mt < 4; ++mt) {
        int row_lo = row0 + mb0 + mt * 16 + qr;
#pragma unroll
        for (int nt = 0; nt < 4; ++nt) {
            int col = col0 + nb0 + nt * 8 + ql * 2;
            float2 bb = *(const float2*)&bias[col];
            size_t off_lo = (size_t)row_lo * D_ + col;
            size_t off_hi = off_lo + (size_t)8 * D_;
            float2 o_lo, o_hi;
            o_lo.x = acc[mt][nt][0] + bb.x;
            o_lo.y = acc[mt][nt][1] + bb.y;
            o_hi.x = acc[mt][nt][2] + bb.x;
            o_hi.y = acc[mt][nt][3] + bb.y;
            if (Res) {
                float2 r0 = *(const float2*)&Res[off_lo];
                float2 r1 = *(const float2*)&Res[off_hi];
                o_lo.x += r0.x; o_lo.y += r0.y;
                o_hi.x += r1.x; o_hi.y += r1.y;
            }
            if (rnd) {
                o_lo.x = tf32r(o_lo.x); o_lo.y = tf32r(o_lo.y);
                o_hi.x = tf32r(o_hi.x); o_hi.y = tf32r(o_hi.y);
            }
            *(float2*)&C[off_lo] = o_lo;
            *(float2*)&C[off_hi] = o_hi;
        }
    }
}

// ================ flash attention via tf32 mma.sync ========================
// Block: one (b,h), 128 query rows. 8 warps x 16 rows. KV tiles of 128 keys,
// double-buffered cp.async. SMEM stride 68 => conflict-free fragment LDS.
// P@V uses the key-permutation trick: S-acc regs (c0,c2,c1,c3) form the A
// fragment directly when V's B-fragment reads keys (2ql, 2ql+1).
#define AST 68
#define ATS (128 * AST)       // floats per tile buffer

__global__ __launch_bounds__(256) void attn_mma(
    const float* __restrict__ Q, const float* __restrict__ K,
    const float* __restrict__ V, float* __restrict__ O)
{
    extern __shared__ float smf[];
    float* buf[2][2] = { { smf, smf + ATS }, { smf + 2 * ATS, smf + 3 * ATS } };

    const int bz = blockIdx.z, h = blockIdx.y;
    const int q0 = blockIdx.x * 128;
    const int tid = threadIdx.x, wid = tid >> 5, lane = tid & 31;
    const int qr = lane >> 2, ql = lane & 3;
    const int mrow = wid * 16;

    const float* Qg = Q + (((size_t)bz * L_ + q0) * H_ + h) * KD_;
    const float* Kg = K + (((size_t)bz * L_) * H_ + h) * KD_;
    const float* Vg = V + (((size_t)bz * L_) * H_ + h) * KD_;

    // ---- stage Q through buf[0][0], build pre-scaled A fragments ----
#pragma unroll
    for (int i = 0; i < 8; ++i) {
        int f = i * 256 + tid;
        int r = f >> 4, c4 = f & 15;
        *(float4*)&buf[0][0][r * AST + c4 * 4] =
            *(const float4*)(Qg + (size_t)r * (H_ * KD_) + c4 * 4);
    }
    __syncthreads();
    uint32_t qf[8][4];
#pragma unroll
    for (int ks = 0; ks < 8; ++ks) {
        qf[ks][0] = __float_as_uint(0.125f * buf[0][0][(mrow + qr) * AST + ks * 8 + ql]);
        qf[ks][1] = __float_as_uint(0.125f * buf[0][0][(mrow + qr + 8) * AST + ks * 8 + ql]);
        qf[ks][2] = __float_as_uint(0.125f * buf[0][0][(mrow + qr) * AST + ks * 8 + ql + 4]);
        qf[ks][3] = __float_as_uint(0.125f * buf[0][0][(mrow + qr + 8) * AST + ks * 8 + ql + 4]);
    }
    __syncthreads();

    float oacc[8][4];
#pragma unroll
    for (int nt = 0; nt < 8; ++nt)
#pragma unroll
        for (int r = 0; r < 4; ++r) oacc[nt][r] = 0.f;
    float m0 = -INFINITY, m1 = -INFINITY, l0 = 0.f, l1 = 0.f;

    // per-thread load slots (8 x float4 per operand per tile)
    int lr[8], lc[8];
#pragma unroll
    for (int i = 0; i < 8; ++i) {
        int f = i * 256 + tid;
        lr[i] = f >> 4;
        lc[i] = (f & 15) * 4;
    }

    // preload tile 0
    {
        uint32_t kd = smem_u32(buf[0][0]);
        uint32_t vd = smem_u32(buf[0][1]);
#pragma unroll
        for (int i = 0; i < 8; ++i) {
            size_t goff = (size_t)lr[i] * (H_ * KD_) + lc[i];
            uint32_t soff = (uint32_t)(lr[i] * AST + lc[i]) * 4u;
            CP_ASYNC16(kd + soff, Kg + goff);
            CP_ASYNC16(vd + soff, Vg + goff);
        }
        CP_COMMIT();
    }

    const int NT = L_ / 128;     // 16 kv tiles
    for (int t = 0; t < NT; ++t) {
        CP_WAIT_ALL();
        __syncthreads();
        if (t + 1 < NT) {
            const int nb = (t + 1) & 1;
            uint32_t kd = smem_u32(buf[nb][0]);
            uint32_t vd = smem_u32(buf[nb][1]);
            const float* Kn = Kg + (size_t)(t + 1) * 128 * (H_ * KD_);
            const float* Vn = Vg + (size_t)(t + 1) * 128 * (H_ * KD_);
#pragma unroll
            for (int i = 0; i < 8; ++i) {
                size_t goff = (size_t)lr[i] * (H_ * KD_) + lc[i];
                uint32_t soff = (uint32_t)(lr[i] * AST + lc[i]) * 4u;
                CP_ASYNC16(kd + soff, Kn + goff);
                CP_ASYNC16(vd + soff, Vn + goff);
            }
            CP_COMMIT();
        }
        const float* Kc = buf[t & 1][0];
        const float* Vc = buf[t & 1][1];

        // ---- S = (Q/8) @ K^T : 16 n-tiles of 8 keys ----
        float sacc[16][4];
#pragma unroll
        for (int nt = 0; nt < 16; ++nt)
#pragma unroll
            for (int r = 0; r < 4; ++r) sacc[nt][r] = 0.f;
#pragma unroll
        for (int ks = 0; ks < 8; ++ks) {
#pragma unroll
            for (int nt = 0; nt < 16; ++nt) {
                int rb = (nt * 8 + qr) * AST + ks * 8 + ql;
                uint32_t b0 = __float_as_uint(Kc[rb]);
                uint32_t b1 = __float_as_uint(Kc[rb + 4]);
                mma_tf32_4(sacc[nt], qf[ks][0], qf[ks][1], qf[ks][2], qf[ks][3], b0, b1);
            }
        }

        // ---- online softmax ----
        float tm0 = -INFINITY, tm1 = -INFINITY;
#pragma unroll
        for (int nt = 0; nt < 16; ++nt) {
            tm0 = fmaxf(tm0, fmaxf(sacc[nt][0], sacc[nt][1]));
            tm1 = fmaxf(tm1, fmaxf(sacc[nt][2], sacc[nt][3]));
        }
        tm0 = fmaxf(tm0, __shfl_xor_sync(0xffffffff, tm0, 1));
        tm0 = fmaxf(tm0, __shfl_xor_sync(0xffffffff, tm0, 2));
        tm1 = fmaxf(tm1, __shfl_xor_sync(0xffffffff, tm1, 1));
        tm1 = fmaxf(tm1, __shfl_xor_sync(0xffffffff, tm1, 2));

        float mn0 = fmaxf(m0, tm0), mn1 = fmaxf(m1, tm1);
        float c0 = __expf(m0 - mn0), c1 = __expf(m1 - mn1);
        l0 *= c0; l1 *= c1;
#pragma unroll
        for (int nt = 0; nt < 8; ++nt) {
            oacc[nt][0] *= c0; oacc[nt][1] *= c0;
            oacc[nt][2] *= c1; oacc[nt][3] *= c1;
        }
        m0 = mn0; m1 = mn1;

#pragma unroll
        for (int nt = 0; nt < 16; ++nt) {
            float p0 = __expf(sacc[nt][0] - m0);
            float p1 = __expf(sacc[nt][1] - m0);
            float p2 = __expf(sacc[nt][2] - m1);
            float p3 = __expf(sacc[nt][3] - m1);
            l0 += p0 + p1;
            l1 += p2 + p3;
            sacc[nt][0] = tf32r(p0);
            sacc[nt][1] = tf32r(p1);
            sacc[nt][2] = tf32r(p2);
            sacc[nt][3] = tf32r(p3);
        }

        // ---- O += P @ V (key-permuted B fragments) ----
#pragma unroll
        for (int g = 0; g < 16; ++g) {
            uint32_t a0 = __float_as_uint(sacc[g][0]);
            uint32_t a1 = __float_as_uint(sacc[g][2]);
            uint32_t a2 = __float_as_uint(sacc[g][1]);
            uint32_t a3 = __float_as_uint(sacc[g][3]);
#pragma unroll
            for (int nt = 0; nt < 8; ++nt) {
                uint32_t b0 = __float_as_uint(Vc[(g * 8 + 2 * ql) * AST + nt * 8 + qr]);
                uint32_t b1 = __float_as_uint(Vc[(g * 8 + 2 * ql + 1) * AST + nt * 8 + qr]);
                mma_tf32_4(oacc[nt], a0, a1, a2, a3, b0, b1);
            }
        }
    }

    // ---- FIX: reduce the softmax denominator across the thread quad ----
    // Each thread's l only covers score columns (2ql, 2ql+1) of each 8-tile;
    // the oacc MMA contraction covers ALL keys. m0/m1 are already quad-
    // consistent, so the partial sums are in the same scale: butterfly-add.
    l0 += __shfl_xor_sync(0xffffffff, l0, 1);
    l0 += __shfl_xor_sync(0xffffffff, l0, 2);
    l1 += __shfl_xor_sync(0xffffffff, l1, 1);
    l1 += __shfl_xor_sync(0xffffffff, l1, 2);

    // ---- normalize + store (tf32-rounded for the Wo GEMM) ----
    float inv0 = 1.f / l0, inv1 = 1.f / l1;
    const int row_lo = q0 + mrow + qr;
    const int row_hi = row_lo + 8;
#pragma unroll
    for (int nt = 0; nt < 8; ++nt) {
        int d = nt * 8 + 2 * ql;
        float2 vlo, vhi;
        vlo.x = tf32r(oacc[nt][0] * inv0);
        vlo.y = tf32r(oacc[nt][1] * inv0);
        vhi.x = tf32r(oacc[nt][2] * inv1);
        vhi.y = tf32r(oacc[nt][3] * inv1);
        *(float2*)&O[(((size_t)bz * L_ + row_lo) * H_ + h) * KD_ + d] = vlo;
        *(float2*)&O[(((size_t)bz * L_ + row_hi) * H_ + h) * KD_ + d] = vhi;
    }
}

// ---------------- elementwise tf32 rounding pass ---------------------------
__global__ __launch_bounds__(256) void round_tf32_kernel(
    const float* __restrict__ X, float* __restrict__ Y)
{
    int i = blockIdx.x * 256 + threadIdx.x;
    float4 v = ((const float4*)X)[i];
    float4 o;
    o.x = tf32r(v.x); o.y = tf32r(v.y); o.z = tf32r(v.z); o.w = tf32r(v.w);
    ((float4*)Y)[i] = o;
}

// ---------------- weight transpose + tf32 round ----------------------------
__global__ __launch_bounds__(256) void transpose4(
    const float* __restrict__ W0, const float* __restrict__ W1,
    const float* __restrict__ W2, const float* __restrict__ W3,
    float* __restrict__ T0, float* __restrict__ T1,
    float* __restrict__ T2, float* __restrict__ T3)
{
    __shared__ float tile[32][33];
    const float* W; float* T;
    switch (blockIdx.z) {
        case 0: W = W0; T = T0; break;
        case 1: W = W1; T = T1; break;
        case 2: W = W2; T = T2; break;
        default: W = W3; T = T3; break;
    }
    int tx = threadIdx.x, ty = threadIdx.y;
    int x = blockIdx.x * 32 + tx;
    int y = blockIdx.y * 32 + ty;
#pragma unroll
    for (int i = 0; i < 4; ++i)
        tile[ty + 8 * i][tx] = W[(size_t)(y + 8 * i) * D_ + x];
    __syncthreads();
    int x2 = blockIdx.y * 32 + tx;
    int y2 = blockIdx.x * 32 + ty;
#pragma unroll
    for (int i = 0; i < 4; ++i)
        T[(size_t)(y2 + 8 * i) * D_ + x2] = tf32r(tile[tx][ty + 8 * i]);
}

// ---------------- LayerNorm: one block per row -----------------------------
__global__ __launch_bounds__(256) void ln_kernel(
    const float* __restrict__ X, const float* __restrict__ gamma,
    const float* __restrict__ beta, float* __restrict__ Y)
{
    const int row = blockIdx.x;
    const int tid = threadIdx.x;
    const float4* x = (const float4*)(X + (size_t)row * D_);
    float4 v = x[tid];

    float s  = v.x + v.y + v.z + v.w;
    float sq = v.x * v.x + v.y * v.y + v.z * v.z + v.w * v.w;
#pragma unroll
    for (int off = 16; off > 0; off >>= 1) {
        s  += __shfl_xor_sync(0xffffffff, s, off);
        sq += __shfl_xor_sync(0xffffffff, sq, off);
    }
    __shared__ float2 red[8];
    if ((tid & 31) == 0) red[tid >> 5] = make_float2(s, sq);
    __syncthreads();
    if (tid < 8) {
        float2 r = red[tid];
#pragma unroll
        for (int off = 4; off > 0; off >>= 1) {
            r.x += __shfl_xor_sync(0xff, r.x, off);
            r.y += __shfl_xor_sync(0xff, r.y, off);
        }
        if (tid == 0) red[0] = r;
    }
    __syncthreads();
    float mean = red[0].x * (1.f / D_);
    float var  = red[0].y * (1.f / D_) - mean * mean;
    float rstd = rsqrtf(var + EPS_);

    float4 g = ((const float4*)gamma)[tid];
    float4 bt = ((const float4*)beta)[tid];
    float4 o;
    o.x = (v.x - mean) * rstd * g.x + bt.x;
    o.y = (v.y - mean) * rstd * g.y + bt.y;
    o.z = (v.z - mean) * rstd * g.z + bt.z;
    o.w = (v.w - mean) * rstd * g.w + bt.w;
    ((float4*)(Y + (size_t)row * D_))[tid] = o;
}

// ---------------- host launch ----------------------------------------------
#define ATTN_SMEM (4 * ATS * 4)   // 139264 bytes

extern "C" void kernel_launch(void* const* d_in, const int* in_sizes, int n_in,
                              void* d_out, int out_size)
{
    const float* queries = (const float*)d_in[0];
    const float* Wq = (const float*)d_in[1];
    const float* bq = (const float*)d_in[2];
    const float* Wk = (const float*)d_in[3];
    const float* bk = (const float*)d_in[4];
    const float* Wv = (const float*)d_in[5];
    const float* bv = (const float*)d_in[6];
    const float* Wo = (const float*)d_in[7];
    const float* bo = (const float*)d_in[8];
    const float* gamma = (const float*)d_in[9];
    const float* beta  = (const float*)d_in[10];

    float *q, *k, *v, *o, *res, *qr, *wqt, *wkt, *wvt, *wot;
    cudaGetSymbolAddress((void**)&q,   g_q);
    cudaGetSymbolAddress((void**)&k,   g_k);
    cudaGetSymbolAddress((void**)&v,   g_v);
    cudaGetSymbolAddress((void**)&o,   g_o);
    cudaGetSymbolAddress((void**)&res, g_res);
    cudaGetSymbolAddress((void**)&qr,  g_qr);
    cudaGetSymbolAddress((void**)&wqt, g_wqt);
    cudaGetSymbolAddress((void**)&wkt, g_wkt);
    cudaGetSymbolAddress((void**)&wvt, g_wvt);
    cudaGetSymbolAddress((void**)&wot, g_wot);

    cudaFuncSetAttribute(attn_mma, cudaFuncAttributeMaxDynamicSharedMemorySize,
                         ATTN_SMEM);

    round_tf32_kernel<<<(M_ * D_) / (256 * 4), 256>>>(queries, qr);
    transpose4<<<dim3(32, 32, 4), dim3(32, 8)>>>(Wq, Wk, Wv, Wo, wqt, wkt, wvt, wot);

    dim3 gGrid(D_ / 128, M_ / 128);   // (8, 64)
    gemm_mma<<<gGrid, 256>>>(qr, wqt, bq, nullptr, q, 1);
    gemm_mma<<<gGrid, 256>>>(qr, wkt, bk, nullptr, k, 1);
    gemm_mma<<<gGrid, 256>>>(qr, wvt, bv, nullptr, v, 1);

    attn_mma<<<dim3(L_ / 128, H_, B_), 256, ATTN_SMEM>>>(q, k, v, o);

    gemm_mma<<<gGrid, 256>>>(o, wot, bo, queries, res, 0);

    ln_kernel<<<M_, 256>>>(res, gamma, beta, (float*)d_out);
}